// round 2
// baseline (speedup 1.0000x reference)
#include <cuda_runtime.h>

// VINeuralODE: B=128 samples, D=32, H=128, 8 Dopri5 steps (6 field evals each).
// trace identity: dlogpdt = -tr(W3 D2 W2 D1 W1) = -sum_{j,k} d1_j M[j,k] d2_k,
//   M[j,k] = (W1@W3)[j,k] * W2[k,j]  (input independent -> precomputed once).
// One block/sample, 256 threads, pair layout (j=tid>>1, h=tid&1), weights in regs.
// 3 barriers per field eval; trace/KL reductions deferred to a per-step epilogue.

#define Dd 32
#define Hh 128
#define NSTEPS 8

__device__ __align__(16) float d_M[Hh * Hh];

__constant__ float c_C[6] = {0.0f, 0.2f, 0.3f, 0.8f, 0.88888888888888888f, 1.0f};

__global__ void precompute_M_kernel(const float* __restrict__ W1,
                                    const float* __restrict__ W2,
                                    const float* __restrict__ W3) {
    int jj = blockIdx.x;   // column of M
    int kk = threadIdx.x;  // row of M
    float a = 0.f;
#pragma unroll
    for (int i = 0; i < Dd; ++i)
        a += W1[kk * Dd + i] * W3[i * Hh + jj];
    d_M[kk * Hh + jj] = a * W2[jj * Hh + kk];
}

__device__ __forceinline__ float ftanh(float x) {
    // tanh(x) = 1 - 2/(exp(2x)+1); MUFU.EX2 + MUFU.RCP path, ~1e-6 rel err.
    float e = __expf(2.0f * x);
    return 1.0f - __fdividef(2.0f, e + 1.0f);
}

__global__ __launch_bounds__(256, 1)
void ode_kernel(const float* __restrict__ x0,
                const float* __restrict__ W1,
                const float* __restrict__ u1,
                const float* __restrict__ b1,
                const float* __restrict__ W2,
                const float* __restrict__ b2,
                const float* __restrict__ W3,
                const float* __restrict__ b3,
                const float* __restrict__ prec,
                float* __restrict__ out, int B) {
    const int s    = blockIdx.x;
    const int tid  = threadIdx.x;
    const int j    = tid >> 1;       // owned H-row (0..127)
    const int h    = tid & 1;        // half (0/1); partner = lane^1 (same warp)
    const int lane = tid & 31;
    const int r3   = tid >> 3;       // owned D-row for W3 (0..31), 8 lanes each
    const int seg  = tid & 7;        // 16-col segment of W3 row
    const float dt = 1.0f / NSTEPS;
    const float HALF_LOG2PI = 0.9189385332046727f;

    __shared__ __align__(16) float sh_xs[Dd];
    __shared__ __align__(16) float sh_h1[Hh];
    __shared__ __align__(16) float sh_h2[Hh];
    __shared__ __align__(16) float sh_d2[Hh];
    __shared__ float sh_tp[6][256];     // raw per-thread trace partials per stage
    __shared__ float sh_k[6][34];
    __shared__ float sh_y[34];
    __shared__ float sh_xh[6][Dd];      // xs snapshot per stage (for KL epilogue)
    __shared__ float b1s[Hh], u1s[Hh], b2s[Hh], b3s[Dd], precs[Dd];

    // ---- register-resident weights ----
    float w1h[16];   // W1[j, h*16 .. +15]
    float w2h[64];   // W2[j, h*64 .. +63]
    float wmh[64];   // M [j, h*64 .. +63]
    float w3r[16];   // W3[r3, seg*16 .. +15]
    {
        const float4* p = (const float4*)(W1 + j * Dd + h * 16);
#pragma unroll
        for (int i = 0; i < 4; ++i) {
            float4 v = p[i];
            w1h[4*i] = v.x; w1h[4*i+1] = v.y; w1h[4*i+2] = v.z; w1h[4*i+3] = v.w;
        }
    }
    {
        const float4* p = (const float4*)(W2 + j * Hh + h * 64);
#pragma unroll
        for (int i = 0; i < 16; ++i) {
            float4 v = p[i];
            w2h[4*i] = v.x; w2h[4*i+1] = v.y; w2h[4*i+2] = v.z; w2h[4*i+3] = v.w;
        }
    }
    {
        const float4* p = (const float4*)(d_M + j * Hh + h * 64);
#pragma unroll
        for (int i = 0; i < 16; ++i) {
            float4 v = p[i];
            wmh[4*i] = v.x; wmh[4*i+1] = v.y; wmh[4*i+2] = v.z; wmh[4*i+3] = v.w;
        }
    }
    {
        const float4* p = (const float4*)(W3 + r3 * Hh + seg * 16);
#pragma unroll
        for (int i = 0; i < 4; ++i) {
            float4 v = p[i];
            w3r[4*i] = v.x; w3r[4*i+1] = v.y; w3r[4*i+2] = v.z; w3r[4*i+3] = v.w;
        }
    }
    if (tid < Hh) { b1s[tid] = b1[tid]; u1s[tid] = u1[tid]; b2s[tid] = b2[tid]; }
    if (tid < Dd) { b3s[tid] = b3[tid]; precs[tid] = prec[tid]; }
    if (tid < 34) {
        float yv = (tid < Dd) ? x0[s * Dd + tid] : 0.f;
        sh_y[tid] = yv;
        if (tid < Dd) sh_xs[tid] = yv;
    }
    __syncthreads();

    for (int step = 0; step < NSTEPS; ++step) {
        float t0 = (float)step * dt;
#pragma unroll 1
        for (int st = 0; st < 6; ++st) {
            float ts = t0 + c_C[st] * dt;

            // ---- phase A: h1 via pair-split dot + shfl combine ----
            if (tid < Dd) sh_xh[st][tid] = sh_xs[tid];   // snapshot for KL epilogue
            float d1v;
            {
                float a0 = 0.f, a1 = 0.f;
#pragma unroll
                for (int i = 0; i < 16; i += 8) {
                    float4 xa = *(const float4*)(sh_xs + h * 16 + i);
                    float4 xb = *(const float4*)(sh_xs + h * 16 + i + 4);
                    a0 += w1h[i]   * xa.x + w1h[i+1] * xa.y + w1h[i+2] * xa.z + w1h[i+3] * xa.w;
                    a1 += w1h[i+4] * xb.x + w1h[i+5] * xb.y + w1h[i+6] * xb.z + w1h[i+7] * xb.w;
                }
                float a = a0 + a1;
                a += __shfl_xor_sync(0xffffffffu, a, 1);
                a += b1s[j] + ts * u1s[j];
                float h1 = ftanh(a);
                d1v = 1.f - h1 * h1;
                if (h == 0) sh_h1[j] = h1;
            }
            __syncthreads();

            // ---- phase B: h2 via pair-split 64-dot (4 accumulators) + shfl ----
            float h2v, d2v;
            {
                float a0 = 0.f, a1 = 0.f, a2 = 0.f, a3 = 0.f;
                const float4* hp = (const float4*)(sh_h1 + h * 64);
#pragma unroll
                for (int i = 0; i < 16; i += 4) {
                    float4 v0 = hp[i], v1 = hp[i+1], v2 = hp[i+2], v3 = hp[i+3];
                    a0 += w2h[4*i]    * v0.x + w2h[4*i+1]  * v0.y + w2h[4*i+2]  * v0.z + w2h[4*i+3]  * v0.w;
                    a1 += w2h[4*i+4]  * v1.x + w2h[4*i+5]  * v1.y + w2h[4*i+6]  * v1.z + w2h[4*i+7]  * v1.w;
                    a2 += w2h[4*i+8]  * v2.x + w2h[4*i+9]  * v2.y + w2h[4*i+10] * v2.z + w2h[4*i+11] * v2.w;
                    a3 += w2h[4*i+12] * v3.x + w2h[4*i+13] * v3.y + w2h[4*i+14] * v3.z + w2h[4*i+15] * v3.w;
                }
                float b = (a0 + a1) + (a2 + a3);
                b += __shfl_xor_sync(0xffffffffu, b, 1);
                b += b2s[j];
                h2v = ftanh(b);
                d2v = 1.f - h2v * h2v;
                if (h == 0) { sh_h2[j] = h2v; sh_d2[j] = d2v; }
            }
            __syncthreads();

            // ---- phase C: trace partial (M@d2 half-dot) + dxdt + next xs ----
            {
                float a0 = 0.f, a1 = 0.f, a2 = 0.f, a3 = 0.f;
                const float4* dp = (const float4*)(sh_d2 + h * 64);
#pragma unroll
                for (int i = 0; i < 16; i += 4) {
                    float4 v0 = dp[i], v1 = dp[i+1], v2 = dp[i+2], v3 = dp[i+3];
                    a0 += wmh[4*i]    * v0.x + wmh[4*i+1]  * v0.y + wmh[4*i+2]  * v0.z + wmh[4*i+3]  * v0.w;
                    a1 += wmh[4*i+4]  * v1.x + wmh[4*i+5]  * v1.y + wmh[4*i+6]  * v1.z + wmh[4*i+7]  * v1.w;
                    a2 += wmh[4*i+8]  * v2.x + wmh[4*i+9]  * v2.y + wmh[4*i+10] * v2.z + wmh[4*i+11] * v2.w;
                    a3 += wmh[4*i+12] * v3.x + wmh[4*i+13] * v3.y + wmh[4*i+14] * v3.z + wmh[4*i+15] * v3.w;
                }
                sh_tp[st][tid] = d1v * ((a0 + a1) + (a2 + a3));

                // dxdt: 8-lane segment reduction of W3 row r3
                float c0 = 0.f, c1 = 0.f;
                const float4* h2p = (const float4*)(sh_h2 + seg * 16);
#pragma unroll
                for (int i = 0; i < 4; i += 2) {
                    float4 v0 = h2p[i], v1 = h2p[i+1];
                    c0 += w3r[4*i]   * v0.x + w3r[4*i+1] * v0.y + w3r[4*i+2] * v0.z + w3r[4*i+3] * v0.w;
                    c1 += w3r[4*i+4] * v1.x + w3r[4*i+5] * v1.y + w3r[4*i+6] * v1.z + w3r[4*i+7] * v1.w;
                }
                float accd = c0 + c1;
                accd += __shfl_xor_sync(0xffffffffu, accd, 1);
                accd += __shfl_xor_sync(0xffffffffu, accd, 2);
                accd += __shfl_xor_sync(0xffffffffu, accd, 4);
                if (seg == 0) {
                    float dxv = accd + b3s[r3];
                    sh_k[st][r3] = dxv;
                    if (st < 5) {
                        float acc;
                        switch (st) {
                            case 0: acc = 0.2f * dxv; break;
                            case 1: acc = (3.f/40.f) * sh_k[0][r3] + (9.f/40.f) * dxv; break;
                            case 2: acc = (44.f/45.f) * sh_k[0][r3] + (-56.f/15.f) * sh_k[1][r3]
                                        + (32.f/9.f) * dxv; break;
                            case 3: acc = (19372.f/6561.f) * sh_k[0][r3] + (-25360.f/2187.f) * sh_k[1][r3]
                                        + (64448.f/6561.f) * sh_k[2][r3] + (-212.f/729.f) * dxv; break;
                            default: acc = (9017.f/3168.f) * sh_k[0][r3] + (-355.f/33.f) * sh_k[1][r3]
                                         + (46732.f/5247.f) * sh_k[2][r3] + (49.f/176.f) * sh_k[3][r3]
                                         + (-5103.f/18656.f) * dxv; break;
                        }
                        sh_xs[r3] = sh_y[r3] + dt * acc;
                    }
                }
            }
            __syncthreads();
        }

        // ---- per-step epilogue: warp w (w<6) reduces trace + KL for stage w ----
        {
            int w = tid >> 5;
            if (w < 6) {
                float tsum = 0.f;
#pragma unroll
                for (int q = 0; q < 8; ++q) tsum += sh_tp[w][q * 32 + lane];
                float tss = t0 + c_C[w] * dt;
                float omt = 1.f - tss;
                float xv  = sh_xh[w][lane];
                float dxv = sh_k[w][lane];
                float cA = -0.5f * omt * omt;
                float cB = -0.5f * omt * (1.f + tss);
                float qv = (cA * (-0.5f * xv * xv - HALF_LOG2PI) + cB * (-precs[lane] * xv)) * dxv;
#pragma unroll
                for (int off = 16; off > 0; off >>= 1) {
                    tsum += __shfl_xor_sync(0xffffffffu, tsum, off);
                    qv   += __shfl_xor_sync(0xffffffffu, qv, off);
                }
                if (lane == 0) {
                    sh_k[w][32] = -tsum;              // dlogpdt
                    sh_k[w][33] = qv + omt * (-tsum); // dkldt
                }
            }
        }
        __syncthreads();

        // ---- y update (dopri5 5th-order combination) ----
        if (tid < 34) {
            float acc = sh_y[tid] + dt * ( (35.f/384.f)    * sh_k[0][tid]
                                         + (500.f/1113.f)  * sh_k[2][tid]
                                         + (125.f/192.f)   * sh_k[3][tid]
                                         + (-2187.f/6784.f)* sh_k[4][tid]
                                         + (11.f/84.f)     * sh_k[5][tid] );
            sh_y[tid] = acc;
            if (tid < Dd) sh_xs[tid] = acc;
        }
        __syncthreads();
    }

    // ---- outputs: z, log_px0 + log_det, kl ----
    if (tid < Dd) out[s * Dd + tid] = sh_y[tid];
    if (tid < 32) {
        float xv = x0[s * Dd + lane];
        float lp = -0.5f * xv * xv - HALF_LOG2PI;
#pragma unroll
        for (int off = 16; off > 0; off >>= 1)
            lp += __shfl_xor_sync(0xffffffffu, lp, off);
        if (lane == 0) {
            out[B * Dd + s]     = lp + sh_y[32];
            out[B * Dd + B + s] = sh_y[33];
        }
    }
}

extern "C" void kernel_launch(void* const* d_in, const int* in_sizes, int n_in,
                              void* d_out, int out_size) {
    const float* x0   = (const float*)d_in[0];
    const float* W1   = (const float*)d_in[1];
    const float* u1   = (const float*)d_in[2];
    const float* b1   = (const float*)d_in[3];
    const float* W2   = (const float*)d_in[4];
    const float* b2   = (const float*)d_in[5];
    const float* W3   = (const float*)d_in[6];
    const float* b3   = (const float*)d_in[7];
    const float* prec = (const float*)d_in[8];
    float* out = (float*)d_out;
    const int B = in_sizes[0] / Dd;

    precompute_M_kernel<<<Hh, Hh>>>(W1, W2, W3);
    ode_kernel<<<B, 256>>>(x0, W1, u1, b1, W2, b2, W3, b3, prec, out, B);
}

// round 4
// speedup vs baseline: 1.2033x; 1.2033x over previous
#include <cuda_runtime.h>

// VINeuralODE: B=128 samples, D=32, H=128, 8 Dopri5 steps (6 field evals each).
// trace identity: dlogpdt = -tr(W3 D2 W2 D1 W1) = -sum_{j,k} d1_j M[j,k] d2_k,
//   M[j,k] = (W1@W3)[j,k] * W2[k,j]  (input independent -> precomputed once).
// One block/sample, 256 threads. Warp-uniform LDS addressing (1 addr -> 1 wavefront)
// except phase B (2-addr, buys a removed barrier). 4 barriers per field eval.

#define Dd 32
#define Hh 128
#define NSTEPS 8

__device__ __align__(16) float d_M[Hh * Hh];

__constant__ float c_C[6] = {0.0f, 0.2f, 0.3f, 0.8f, 0.88888888888888888f, 1.0f};

__global__ void precompute_M_kernel(const float* __restrict__ W1,
                                    const float* __restrict__ W2,
                                    const float* __restrict__ W3) {
    int jj = blockIdx.x;   // column of M
    int kk = threadIdx.x;  // row of M
    float a = 0.f;
#pragma unroll
    for (int i = 0; i < Dd; ++i)
        a += W1[kk * Dd + i] * W3[i * Hh + jj];
    d_M[kk * Hh + jj] = a * W2[jj * Hh + kk];
}

__device__ __forceinline__ float ftanh(float x) {
    // tanh(x) = 1 - 2/(exp(2x)+1); MUFU.EX2 + MUFU.RCP path, ~1e-6 rel err.
    float e = __expf(2.0f * x);
    return 1.0f - __fdividef(2.0f, e + 1.0f);
}

__global__ __launch_bounds__(256, 1)
void ode_kernel(const float* __restrict__ x0,
                const float* __restrict__ W1,
                const float* __restrict__ u1,
                const float* __restrict__ b1,
                const float* __restrict__ W2,
                const float* __restrict__ b2,
                const float* __restrict__ W3,
                const float* __restrict__ b3,
                const float* __restrict__ prec,
                float* __restrict__ out, int B) {
    const int s    = blockIdx.x;
    const int tid  = threadIdx.x;
    const int lane = tid & 31;
    const int warp = tid >> 5;
    const int ja   = tid & 127;            // phase A / D row (dup x2)
    const int hd   = tid >> 7;             // phase D half (uniform per warp)
    const int jb   = warp * 16 + (lane & 15); // phase B row
    const int hb   = lane >> 4;            // phase B half (partner = lane^16)
    const float dt = 1.0f / NSTEPS;
    const float HALF_LOG2PI = 0.9189385332046727f;

    __shared__ __align__(16) float sh_xs[Dd];
    __shared__ __align__(16) float sh_h1[Hh];
    __shared__ __align__(16) float sh_h2[Hh];
    __shared__ __align__(16) float sh_d2[Hh];
    __shared__ float sh_dxp[256];       // W3 segment partials
    __shared__ float sh_tp[6][256];     // raw trace partials per stage
    __shared__ float sh_k[6][34];
    __shared__ float sh_y[34];
    __shared__ float sh_xh[6][Dd];      // x snapshot per stage (KL epilogue)
    __shared__ float b1s[Hh], u1s[Hh], b2s[Hh], b3s[Dd], precs[Dd];

    // ---- register-resident weights ----
    float w1r[32];   // W1[ja, 0:32]
    float w2h[64];   // W2[jb, hb*64 : +64]
    float wmh[64];   // M [ja, hd*64 : +64]
    float w3r[16];   // W3[lane, warp*16 : +16]
    {
        const float4* p = (const float4*)(W1 + ja * Dd);
#pragma unroll
        for (int i = 0; i < 8; ++i) {
            float4 v = p[i];
            w1r[4*i] = v.x; w1r[4*i+1] = v.y; w1r[4*i+2] = v.z; w1r[4*i+3] = v.w;
        }
    }
    {
        const float4* p = (const float4*)(W2 + jb * Hh + hb * 64);
#pragma unroll
        for (int i = 0; i < 16; ++i) {
            float4 v = p[i];
            w2h[4*i] = v.x; w2h[4*i+1] = v.y; w2h[4*i+2] = v.z; w2h[4*i+3] = v.w;
        }
    }
    {
        const float4* p = (const float4*)(d_M + ja * Hh + hd * 64);
#pragma unroll
        for (int i = 0; i < 16; ++i) {
            float4 v = p[i];
            wmh[4*i] = v.x; wmh[4*i+1] = v.y; wmh[4*i+2] = v.z; wmh[4*i+3] = v.w;
        }
    }
    {
        const float4* p = (const float4*)(W3 + lane * Hh + warp * 16);
#pragma unroll
        for (int i = 0; i < 4; ++i) {
            float4 v = p[i];
            w3r[4*i] = v.x; w3r[4*i+1] = v.y; w3r[4*i+2] = v.z; w3r[4*i+3] = v.w;
        }
    }
    if (tid < Hh) { b1s[tid] = b1[tid]; u1s[tid] = u1[tid]; b2s[tid] = b2[tid]; }
    if (tid < Dd) { b3s[tid] = b3[tid]; precs[tid] = prec[tid]; }
    if (tid < 34) {
        float yv = (tid < Dd) ? x0[s * Dd + tid] : 0.f;
        sh_y[tid] = yv;
        if (tid < Dd) sh_xs[tid] = yv;
    }
    __syncthreads();

    // dopri5 k registers (warp 0 lanes, dim = lane)
    float k0 = 0.f, k1 = 0.f, k2 = 0.f, k3 = 0.f, k4 = 0.f;

    for (int step = 0; step < NSTEPS; ++step) {
        float t0 = (float)step * dt;
#pragma unroll 1
        for (int st = 0; st < 6; ++st) {
            float ts = t0 + c_C[st] * dt;

            // ---- phase A: h1 (all 256 dup over halves) ----
            if (tid < Dd) sh_xh[st][tid] = sh_xs[tid];   // snapshot for KL epilogue
            float d1v;
            {
                float a0 = 0.f, a1 = 0.f, a2 = 0.f, a3 = 0.f;
                const float4* xp = (const float4*)sh_xs;
#pragma unroll
                for (int i = 0; i < 8; i += 4) {
                    float4 v0 = xp[i], v1 = xp[i+1], v2 = xp[i+2], v3 = xp[i+3];
                    a0 += w1r[4*i]    * v0.x + w1r[4*i+1]  * v0.y + w1r[4*i+2]  * v0.z + w1r[4*i+3]  * v0.w;
                    a1 += w1r[4*i+4]  * v1.x + w1r[4*i+5]  * v1.y + w1r[4*i+6]  * v1.z + w1r[4*i+7]  * v1.w;
                    a2 += w1r[4*i+8]  * v2.x + w1r[4*i+9]  * v2.y + w1r[4*i+10] * v2.z + w1r[4*i+11] * v2.w;
                    a3 += w1r[4*i+12] * v3.x + w1r[4*i+13] * v3.y + w1r[4*i+14] * v3.z + w1r[4*i+15] * v3.w;
                }
                float a = ((a0 + a1) + (a2 + a3)) + b1s[ja] + ts * u1s[ja];
                float h1 = ftanh(a);
                d1v = 1.f - h1 * h1;
                if (tid < Hh) sh_h1[tid] = h1;
            }
            __syncthreads();

            // ---- phase B: h2 half-dot + intra-warp shfl combine ----
            {
                float a0 = 0.f, a1 = 0.f, a2 = 0.f, a3 = 0.f;
                const float4* hp = (const float4*)(sh_h1 + hb * 64);
#pragma unroll
                for (int i = 0; i < 16; i += 4) {
                    float4 v0 = hp[i], v1 = hp[i+1], v2 = hp[i+2], v3 = hp[i+3];
                    a0 += w2h[4*i]    * v0.x + w2h[4*i+1]  * v0.y + w2h[4*i+2]  * v0.z + w2h[4*i+3]  * v0.w;
                    a1 += w2h[4*i+4]  * v1.x + w2h[4*i+5]  * v1.y + w2h[4*i+6]  * v1.z + w2h[4*i+7]  * v1.w;
                    a2 += w2h[4*i+8]  * v2.x + w2h[4*i+9]  * v2.y + w2h[4*i+10] * v2.z + w2h[4*i+11] * v2.w;
                    a3 += w2h[4*i+12] * v3.x + w2h[4*i+13] * v3.y + w2h[4*i+14] * v3.z + w2h[4*i+15] * v3.w;
                }
                float b = (a0 + a1) + (a2 + a3);
                b += __shfl_xor_sync(0xffffffffu, b, 16);
                b += b2s[jb];
                float h2 = ftanh(b);
                if (hb == 0) { sh_h2[jb] = h2; sh_d2[jb] = 1.f - h2 * h2; }
            }
            __syncthreads();

            // ---- phase D: trace half-dot (store raw) + W3 segment dot ----
            {
                float a0 = 0.f, a1 = 0.f, a2 = 0.f, a3 = 0.f;
                const float4* dp = (const float4*)(sh_d2 + hd * 64);
#pragma unroll
                for (int i = 0; i < 16; i += 4) {
                    float4 v0 = dp[i], v1 = dp[i+1], v2 = dp[i+2], v3 = dp[i+3];
                    a0 += wmh[4*i]    * v0.x + wmh[4*i+1]  * v0.y + wmh[4*i+2]  * v0.z + wmh[4*i+3]  * v0.w;
                    a1 += wmh[4*i+4]  * v1.x + wmh[4*i+5]  * v1.y + wmh[4*i+6]  * v1.z + wmh[4*i+7]  * v1.w;
                    a2 += wmh[4*i+8]  * v2.x + wmh[4*i+9]  * v2.y + wmh[4*i+10] * v2.z + wmh[4*i+11] * v2.w;
                    a3 += wmh[4*i+12] * v3.x + wmh[4*i+13] * v3.y + wmh[4*i+14] * v3.z + wmh[4*i+15] * v3.w;
                }
                sh_tp[st][tid] = d1v * ((a0 + a1) + (a2 + a3));

                // W3[lane, warp*16:+16] . h2[warp*16:+16]  (uniform address per warp)
                float c0 = 0.f, c1 = 0.f;
                const float4* h2p = (const float4*)(sh_h2 + warp * 16);
                float4 v0 = h2p[0], v1 = h2p[1], v2 = h2p[2], v3 = h2p[3];
                c0 += w3r[0]  * v0.x + w3r[1]  * v0.y + w3r[2]  * v0.z + w3r[3]  * v0.w;
                c1 += w3r[4]  * v1.x + w3r[5]  * v1.y + w3r[6]  * v1.z + w3r[7]  * v1.w;
                c0 += w3r[8]  * v2.x + w3r[9]  * v2.y + w3r[10] * v2.z + w3r[11] * v2.w;
                c1 += w3r[12] * v3.x + w3r[13] * v3.y + w3r[14] * v3.z + w3r[15] * v3.w;
                sh_dxp[tid] = c0 + c1;
            }
            __syncthreads();

            // ---- phase E (warp 0): dxdt assembly, k store, next xs ----
            if (warp == 0) {
                float p0 = sh_dxp[lane]       + sh_dxp[lane + 32];
                float p1 = sh_dxp[lane + 64]  + sh_dxp[lane + 96];
                float p2 = sh_dxp[lane + 128] + sh_dxp[lane + 160];
                float p3 = sh_dxp[lane + 192] + sh_dxp[lane + 224];
                float dxv = ((p0 + p1) + (p2 + p3)) + b3s[lane];
                sh_k[st][lane] = dxv;
                float yv = sh_y[lane];
                float acc;
                switch (st) {
                    case 0: k0 = dxv; acc = 0.2f * k0; break;
                    case 1: k1 = dxv; acc = (3.f/40.f) * k0 + (9.f/40.f) * k1; break;
                    case 2: k2 = dxv; acc = (44.f/45.f) * k0 + (-56.f/15.f) * k1 + (32.f/9.f) * k2; break;
                    case 3: k3 = dxv; acc = (19372.f/6561.f) * k0 + (-25360.f/2187.f) * k1
                                          + (64448.f/6561.f) * k2 + (-212.f/729.f) * k3; break;
                    case 4: k4 = dxv; acc = (9017.f/3168.f) * k0 + (-355.f/33.f) * k1
                                          + (46732.f/5247.f) * k2 + (49.f/176.f) * k3
                                          + (-5103.f/18656.f) * k4; break;
                    default: acc = 0.f; break;
                }
                if (st < 5) sh_xs[lane] = yv + dt * acc;
            }
            __syncthreads();
        }

        // ---- per-step epilogue: warps 0-5 reduce trace+KL for stage w;
        //      warp 6 does dopri5 y-update for dims 0-31 concurrently ----
        if (warp < 6) {
            int w = warp;
            float t0a = sh_tp[w][lane]       + sh_tp[w][lane + 32];
            float t1a = sh_tp[w][lane + 64]  + sh_tp[w][lane + 96];
            float t2a = sh_tp[w][lane + 128] + sh_tp[w][lane + 160];
            float t3a = sh_tp[w][lane + 192] + sh_tp[w][lane + 224];
            float tsum = (t0a + t1a) + (t2a + t3a);
            float tss = t0 + c_C[w] * dt;
            float omt = 1.f - tss;
            float xv  = sh_xh[w][lane];
            float dxv = sh_k[w][lane];
            float cA = -0.5f * omt * omt;
            float cB = -0.5f * omt * (1.f + tss);
            float qv = (cA * (-0.5f * xv * xv - HALF_LOG2PI) + cB * (-precs[lane] * xv)) * dxv;
#pragma unroll
            for (int off = 16; off > 0; off >>= 1) {
                tsum += __shfl_xor_sync(0xffffffffu, tsum, off);
                qv   += __shfl_xor_sync(0xffffffffu, qv, off);
            }
            if (lane == 0) {
                sh_k[w][32] = -tsum;              // dlogpdt
                sh_k[w][33] = qv + omt * (-tsum); // dkldt
            }
        } else if (warp == 6) {
            if (lane < Dd) {
                float acc = sh_y[lane] + dt * ( (35.f/384.f)    * sh_k[0][lane]
                                              + (500.f/1113.f)  * sh_k[2][lane]
                                              + (125.f/192.f)   * sh_k[3][lane]
                                              + (-2187.f/6784.f)* sh_k[4][lane]
                                              + (11.f/84.f)     * sh_k[5][lane] );
                sh_y[lane] = acc;
                sh_xs[lane] = acc;
            }
        }
        __syncthreads();

        // dims 32 (logdet), 33 (kl)
        if (tid < 2) {
            int d = 32 + tid;
            sh_y[d] += dt * ( (35.f/384.f)    * sh_k[0][d]
                            + (500.f/1113.f)  * sh_k[2][d]
                            + (125.f/192.f)   * sh_k[3][d]
                            + (-2187.f/6784.f)* sh_k[4][d]
                            + (11.f/84.f)     * sh_k[5][d] );
        }
        __syncthreads();
    }

    // ---- outputs: z, log_px0 + log_det, kl ----
    if (tid < Dd) out[s * Dd + tid] = sh_y[tid];
    if (tid < 32) {
        float xv = x0[s * Dd + lane];
        float lp = -0.5f * xv * xv - HALF_LOG2PI;
#pragma unroll
        for (int off = 16; off > 0; off >>= 1)
            lp += __shfl_xor_sync(0xffffffffu, lp, off);
        if (lane == 0) {
            out[B * Dd + s]     = lp + sh_y[32];
            out[B * Dd + B + s] = sh_y[33];
        }
    }
}

extern "C" void kernel_launch(void* const* d_in, const int* in_sizes, int n_in,
                              void* d_out, int out_size) {
    const float* x0   = (const float*)d_in[0];
    const float* W1   = (const float*)d_in[1];
    const float* u1   = (const float*)d_in[2];
    const float* b1   = (const float*)d_in[3];
    const float* W2   = (const float*)d_in[4];
    const float* b2   = (const float*)d_in[5];
    const float* W3   = (const float*)d_in[6];
    const float* b3   = (const float*)d_in[7];
    const float* prec = (const float*)d_in[8];
    float* out = (float*)d_out;
    const int B = in_sizes[0] / Dd;

    precompute_M_kernel<<<Hh, Hh>>>(W1, W2, W3);
    ode_kernel<<<B, 256>>>(x0, W1, u1, b1, W2, b2, W3, b3, prec, out, B);
}

// round 6
// speedup vs baseline: 1.4948x; 1.2423x over previous
#include <cuda_runtime.h>

// VINeuralODE: B=128 samples, D=32, H=128, 8 Dopri5 steps x 6 field evals.
// trace identity: dlogpdt = -tr(W3 D2 W2 D1 W1) = -sum_u d1_u (M[u,:]·d2),
//   M[u,k] = (W1@W3)[u,k] * W2[k,u]  (input independent -> precomputed once).
// One block/sample, 256 threads, warp-specialized:
//   warps 0-3 ("compute"): h1 -> h2 -> xs critical path, full weight rows in regs.
//   warps 4-7 ("trace"):   W3 quarter-dots (feed warp0) + full M-row trace dots,
//                          overlapped with compute via named bar.sync/bar.arrive.
// All KL/logdet reductions deferred to one final epilogue (linear accumulations).

#define Dd 32
#define Hh 128
#define NSTEPS 8
#define NST 48   // total stages

__device__ __align__(16) float d_M[Hh * Hh];

__constant__ float c_C[6]  = {0.0f, 0.2f, 0.3f, 0.8f, 0.88888888888888888f, 1.0f};
__constant__ float c_BW[6] = {35.0f/384.0f, 0.0f, 500.0f/1113.0f, 125.0f/192.0f,
                              -2187.0f/6784.0f, 11.0f/84.0f};

#define BAR_SYNC(id, cnt)   asm volatile("bar.sync %0, %1;"   :: "r"(id), "r"(cnt) : "memory")
#define BAR_ARRIVE(id, cnt) asm volatile("bar.arrive %0, %1;" :: "r"(id), "r"(cnt) : "memory")

__global__ void precompute_M_kernel(const float* __restrict__ W1,
                                    const float* __restrict__ W2,
                                    const float* __restrict__ W3) {
    int jj = blockIdx.x;   // column of M
    int kk = threadIdx.x;  // row of M
    float a = 0.f;
#pragma unroll
    for (int i = 0; i < Dd; ++i)
        a += W1[kk * Dd + i] * W3[i * Hh + jj];
    d_M[kk * Hh + jj] = a * W2[jj * Hh + kk];
}

__device__ __forceinline__ float ftanh(float x) {
    // tanh(x) = 1 - 2/(exp(2x)+1); MUFU.EX2 + MUFU.RCP path, ~1e-6 rel err.
    float e = __expf(2.0f * x);
    return 1.0f - __fdividef(2.0f, e + 1.0f);
}

__global__ __launch_bounds__(256, 1)
void ode_kernel(const float* __restrict__ x0,
                const float* __restrict__ W1,
                const float* __restrict__ u1,
                const float* __restrict__ b1,
                const float* __restrict__ W2,
                const float* __restrict__ b2,
                const float* __restrict__ W3,
                const float* __restrict__ b3,
                const float* __restrict__ prec,
                float* __restrict__ out, int B) {
    const int s    = blockIdx.x;
    const int tid  = threadIdx.x;
    const int lane = tid & 31;
    const int warp = tid >> 5;
    const float dt = 1.0f / NSTEPS;
    const float HALF_LOG2PI = 0.9189385332046727f;

    __shared__ __align__(16) float sh_xs[Dd];
    __shared__ __align__(16) float sh_h1[Hh];
    __shared__ __align__(16) float sh_d1[2][Hh];
    __shared__ __align__(16) float sh_h2[Hh];
    __shared__ __align__(16) float sh_d2[Hh];
    __shared__ float sh_dxp[Hh];          // W3 quarter partials (by trace warps)
    __shared__ float sh_tw[NST][4];       // per-stage trace warp-sums
    __shared__ float sh_xh[NST][Dd];      // x snapshot per stage
    __shared__ float sh_kd[NST][Dd];      // dxdt per stage
    __shared__ float b1s[Hh], u1s[Hh], b2s[Hh], b3s[Dd], precs[Dd];
    __shared__ float sh_pld[8], sh_pkl[8], sh_lp;

    // ---- common init ----
    if (tid < Hh) { b1s[tid] = b1[tid]; u1s[tid] = u1[tid]; b2s[tid] = b2[tid]; }
    if (tid < Dd) {
        b3s[tid] = b3[tid]; precs[tid] = prec[tid];
        sh_xs[tid] = x0[s * Dd + tid];
    }
    __syncthreads();

    if (warp < 4) {
        // ================= COMPUTE GROUP (threads 0-127), row j = tid =======
        const int j = tid;
        float w1r[Dd];    // W1[j, 0:32]
        float w2r[Hh];    // W2[j, 0:128]
        {
            const float4* p = (const float4*)(W1 + j * Dd);
#pragma unroll
            for (int i = 0; i < 8; ++i) {
                float4 v = p[i];
                w1r[4*i] = v.x; w1r[4*i+1] = v.y; w1r[4*i+2] = v.z; w1r[4*i+3] = v.w;
            }
        }
        {
            const float4* p = (const float4*)(W2 + j * Hh);
#pragma unroll
            for (int i = 0; i < 32; ++i) {
                float4 v = p[i];
                w2r[4*i] = v.x; w2r[4*i+1] = v.y; w2r[4*i+2] = v.z; w2r[4*i+3] = v.w;
            }
        }
        float yv = 0.f, k0 = 0.f, k1 = 0.f, k2 = 0.f, k3 = 0.f, k4 = 0.f;
        if (warp == 0) yv = x0[s * Dd + lane];

        int gst = 0;
        for (int step = 0; step < NSTEPS; ++step) {
            float t0 = (float)step * dt;
#pragma unroll 1
            for (int st = 0; st < 6; ++st, ++gst) {
                float ts = t0 + c_C[st] * dt;

                // ---- W1 window: h1 row j ----
                if (warp == 1) sh_xh[gst][lane] = sh_xs[lane];
                {
                    float a0 = 0.f, a1 = 0.f, a2 = 0.f, a3 = 0.f;
                    const float4* xp = (const float4*)sh_xs;
#pragma unroll
                    for (int i = 0; i < 8; i += 4) {
                        float4 v0 = xp[i], v1 = xp[i+1], v2 = xp[i+2], v3 = xp[i+3];
                        a0 += w1r[4*i]    * v0.x + w1r[4*i+1]  * v0.y + w1r[4*i+2]  * v0.z + w1r[4*i+3]  * v0.w;
                        a1 += w1r[4*i+4]  * v1.x + w1r[4*i+5]  * v1.y + w1r[4*i+6]  * v1.z + w1r[4*i+7]  * v1.w;
                        a2 += w1r[4*i+8]  * v2.x + w1r[4*i+9]  * v2.y + w1r[4*i+10] * v2.z + w1r[4*i+11] * v2.w;
                        a3 += w1r[4*i+12] * v3.x + w1r[4*i+13] * v3.y + w1r[4*i+14] * v3.z + w1r[4*i+15] * v3.w;
                    }
                    float a = ((a0 + a1) + (a2 + a3)) + b1s[j] + ts * u1s[j];
                    float h1 = ftanh(a);
                    sh_h1[j] = h1;
                    sh_d1[gst & 1][j] = 1.f - h1 * h1;
                }
                BAR_SYNC(1, 128);

                // ---- W2 window: h2 row j (full 128-dot, 8 accumulators) ----
                {
                    float a0=0.f,a1=0.f,a2=0.f,a3=0.f,a4=0.f,a5=0.f,a6=0.f,a7=0.f;
                    const float4* hp = (const float4*)sh_h1;
#pragma unroll
                    for (int i = 0; i < 32; i += 8) {
                        float4 v0 = hp[i],   v1 = hp[i+1], v2 = hp[i+2], v3 = hp[i+3];
                        float4 v4 = hp[i+4], v5 = hp[i+5], v6 = hp[i+6], v7 = hp[i+7];
                        a0 += w2r[4*i]    * v0.x + w2r[4*i+1]  * v0.y + w2r[4*i+2]  * v0.z + w2r[4*i+3]  * v0.w;
                        a1 += w2r[4*i+4]  * v1.x + w2r[4*i+5]  * v1.y + w2r[4*i+6]  * v1.z + w2r[4*i+7]  * v1.w;
                        a2 += w2r[4*i+8]  * v2.x + w2r[4*i+9]  * v2.y + w2r[4*i+10] * v2.z + w2r[4*i+11] * v2.w;
                        a3 += w2r[4*i+12] * v3.x + w2r[4*i+13] * v3.y + w2r[4*i+14] * v3.z + w2r[4*i+15] * v3.w;
                        a4 += w2r[4*i+16] * v4.x + w2r[4*i+17] * v4.y + w2r[4*i+18] * v4.z + w2r[4*i+19] * v4.w;
                        a5 += w2r[4*i+20] * v5.x + w2r[4*i+21] * v5.y + w2r[4*i+22] * v5.z + w2r[4*i+23] * v5.w;
                        a6 += w2r[4*i+24] * v6.x + w2r[4*i+25] * v6.y + w2r[4*i+26] * v6.z + w2r[4*i+27] * v6.w;
                        a7 += w2r[4*i+28] * v7.x + w2r[4*i+29] * v7.y + w2r[4*i+30] * v7.z + w2r[4*i+31] * v7.w;
                    }
                    float b = (((a0 + a1) + (a2 + a3)) + ((a4 + a5) + (a6 + a7))) + b2s[j];
                    float h2 = ftanh(b);
                    BAR_SYNC(3, 256);         // trace has consumed previous d2
                    sh_h2[j] = h2;
                    sh_d2[j] = 1.f - h2 * h2;
                }
                BAR_ARRIVE(2, 256);           // signal h2/d2 ready to trace group

                // ---- warp 0: assemble dxdt, dopri5 update ----
                if (warp == 0) {
                    BAR_SYNC(4, 160);         // wait for trace warps' W3 partials
                    float dxv = ((sh_dxp[lane] + sh_dxp[lane + 32])
                               + (sh_dxp[lane + 64] + sh_dxp[lane + 96])) + b3s[lane];
                    sh_kd[gst][lane] = dxv;
                    float acc;
                    switch (st) {
                        case 0: k0 = dxv; acc = 0.2f * k0; break;
                        case 1: k1 = dxv; acc = (3.f/40.f) * k0 + (9.f/40.f) * k1; break;
                        case 2: k2 = dxv; acc = (44.f/45.f) * k0 + (-56.f/15.f) * k1 + (32.f/9.f) * k2; break;
                        case 3: k3 = dxv; acc = (19372.f/6561.f) * k0 + (-25360.f/2187.f) * k1
                                              + (64448.f/6561.f) * k2 + (-212.f/729.f) * k3; break;
                        case 4: k4 = dxv; acc = (9017.f/3168.f) * k0 + (-355.f/33.f) * k1
                                              + (46732.f/5247.f) * k2 + (49.f/176.f) * k3
                                              + (-5103.f/18656.f) * k4; break;
                        default:
                            yv = yv + dt * ( (35.f/384.f)     * k0
                                           + (500.f/1113.f)   * k2
                                           + (125.f/192.f)    * k3
                                           + (-2187.f/6784.f) * k4
                                           + (11.f/84.f)      * dxv );
                            acc = 0.f; break;
                    }
                    sh_xs[lane] = (st < 5) ? (yv + dt * acc) : yv;
                }
                BAR_SYNC(1, 128);             // xs ready for next stage
            }
        }
        // stash final z (avoid relying on regs across the big epilogue sync)
        if (warp == 0) out[s * Dd + lane] = yv;
    } else {
        // ================= TRACE GROUP (threads 128-255), row u = tid-128 ====
        const int u  = tid - 128;
        const int tw = warp - 4;          // 0..3, W3 quarter + tw slot
        float wmr[Hh];    // M[u, 0:128]
        float w3q[Dd];    // W3[u&31, tw*32 : +32]
        {
            const float4* p = (const float4*)(d_M + u * Hh);
#pragma unroll
            for (int i = 0; i < 32; ++i) {
                float4 v = p[i];
                wmr[4*i] = v.x; wmr[4*i+1] = v.y; wmr[4*i+2] = v.z; wmr[4*i+3] = v.w;
            }
        }
        {
            const float4* p = (const float4*)(W3 + (u & 31) * Hh + tw * 32);
#pragma unroll
            for (int i = 0; i < 8; ++i) {
                float4 v = p[i];
                w3q[4*i] = v.x; w3q[4*i+1] = v.y; w3q[4*i+2] = v.z; w3q[4*i+3] = v.w;
            }
        }
        BAR_ARRIVE(3, 256);               // prime "d2 consumed"

#pragma unroll 1
        for (int gst = 0; gst < NST; ++gst) {
            BAR_SYNC(2, 256);             // wait h2/d2 ready

            // ---- W3 quarter dot: row u&31, cols tw*32..+31 (uniform LDS) ----
            {
                float c0 = 0.f, c1 = 0.f, c2 = 0.f, c3 = 0.f;
                const float4* h2p = (const float4*)(sh_h2 + tw * 32);
#pragma unroll
                for (int i = 0; i < 8; i += 4) {
                    float4 v0 = h2p[i], v1 = h2p[i+1], v2 = h2p[i+2], v3 = h2p[i+3];
                    c0 += w3q[4*i]    * v0.x + w3q[4*i+1]  * v0.y + w3q[4*i+2]  * v0.z + w3q[4*i+3]  * v0.w;
                    c1 += w3q[4*i+4]  * v1.x + w3q[4*i+5]  * v1.y + w3q[4*i+6]  * v1.z + w3q[4*i+7]  * v1.w;
                    c2 += w3q[4*i+8]  * v2.x + w3q[4*i+9]  * v2.y + w3q[4*i+10] * v2.z + w3q[4*i+11] * v2.w;
                    c3 += w3q[4*i+12] * v3.x + w3q[4*i+13] * v3.y + w3q[4*i+14] * v3.z + w3q[4*i+15] * v3.w;
                }
                sh_dxp[u] = (c0 + c1) + (c2 + c3);
            }
            BAR_ARRIVE(4, 160);           // release warp 0

            // ---- full M-row trace dot (off critical path) ----
            float val;
            {
                float a0=0.f,a1=0.f,a2=0.f,a3=0.f,a4=0.f,a5=0.f,a6=0.f,a7=0.f;
                const float4* dp = (const float4*)sh_d2;
#pragma unroll
                for (int i = 0; i < 32; i += 8) {
                    float4 v0 = dp[i],   v1 = dp[i+1], v2 = dp[i+2], v3 = dp[i+3];
                    float4 v4 = dp[i+4], v5 = dp[i+5], v6 = dp[i+6], v7 = dp[i+7];
                    a0 += wmr[4*i]    * v0.x + wmr[4*i+1]  * v0.y + wmr[4*i+2]  * v0.z + wmr[4*i+3]  * v0.w;
                    a1 += wmr[4*i+4]  * v1.x + wmr[4*i+5]  * v1.y + wmr[4*i+6]  * v1.z + wmr[4*i+7]  * v1.w;
                    a2 += wmr[4*i+8]  * v2.x + wmr[4*i+9]  * v2.y + wmr[4*i+10] * v2.z + wmr[4*i+11] * v2.w;
                    a3 += wmr[4*i+12] * v3.x + wmr[4*i+13] * v3.y + wmr[4*i+14] * v3.z + wmr[4*i+15] * v3.w;
                    a4 += wmr[4*i+16] * v4.x + wmr[4*i+17] * v4.y + wmr[4*i+18] * v4.z + wmr[4*i+19] * v4.w;
                    a5 += wmr[4*i+20] * v5.x + wmr[4*i+21] * v5.y + wmr[4*i+22] * v5.z + wmr[4*i+23] * v5.w;
                    a6 += wmr[4*i+24] * v6.x + wmr[4*i+25] * v6.y + wmr[4*i+26] * v6.z + wmr[4*i+27] * v6.w;
                    a7 += wmr[4*i+28] * v7.x + wmr[4*i+29] * v7.y + wmr[4*i+30] * v7.z + wmr[4*i+31] * v7.w;
                }
                float dot = (((a0 + a1) + (a2 + a3)) + ((a4 + a5) + (a6 + a7)));
                val = sh_d1[gst & 1][u] * dot;
            }
            BAR_ARRIVE(3, 256);           // d2 consumed; compute may overwrite

            // warp-local reduce, store one scalar per trace warp
#pragma unroll
            for (int off = 16; off > 0; off >>= 1)
                val += __shfl_xor_sync(0xffffffffu, val, off);
            if (lane == 0) sh_tw[gst][tw] = val;
        }
    }
    __syncthreads();

    // ================= FINAL EPILOGUE: 48 stage reductions over 8 warps ======
    {
        float acc_ld = 0.f, acc_kl = 0.f;
#pragma unroll 1
        for (int i = 0; i < 6; ++i) {
            int g = warp + 8 * i;
            int st = g % 6;
            int stp = g / 6;
            float ts = (float)stp * dt + c_C[st] * dt;
            float dlogp = -((sh_tw[g][0] + sh_tw[g][1]) + (sh_tw[g][2] + sh_tw[g][3]));
            float omt = 1.f - ts;
            float cA = -0.5f * omt * omt;
            float cB = -0.5f * omt * (1.f + ts);
            float xv  = sh_xh[g][lane];
            float dxv = sh_kd[g][lane];
            float qv = (cA * (-0.5f * xv * xv - HALF_LOG2PI) + cB * (-precs[lane] * xv)) * dxv;
#pragma unroll
            for (int off = 16; off > 0; off >>= 1)
                qv += __shfl_xor_sync(0xffffffffu, qv, off);
            float bw = c_BW[st];
            acc_ld += bw * dlogp;
            acc_kl += bw * (qv + omt * dlogp);
        }
        if (lane == 0) { sh_pld[warp] = acc_ld; sh_pkl[warp] = acc_kl; }
        if (warp == 1) {
            float xv = x0[s * Dd + lane];
            float lp = -0.5f * xv * xv - HALF_LOG2PI;
#pragma unroll
            for (int off = 16; off > 0; off >>= 1)
                lp += __shfl_xor_sync(0xffffffffu, lp, off);
            if (lane == 0) sh_lp = lp;
        }
    }
    __syncthreads();
    if (tid == 0) {
        float ld = 0.f, kl = 0.f;
#pragma unroll
        for (int w = 0; w < 8; ++w) { ld += sh_pld[w]; kl += sh_pkl[w]; }
        out[B * Dd + s]     = sh_lp + dt * ld;
        out[B * Dd + B + s] = dt * kl;
    }
}

extern "C" void kernel_launch(void* const* d_in, const int* in_sizes, int n_in,
                              void* d_out, int out_size) {
    const float* x0   = (const float*)d_in[0];
    const float* W1   = (const float*)d_in[1];
    const float* u1   = (const float*)d_in[2];
    const float* b1   = (const float*)d_in[3];
    const float* W2   = (const float*)d_in[4];
    const float* b2   = (const float*)d_in[5];
    const float* W3   = (const float*)d_in[6];
    const float* b3   = (const float*)d_in[7];
    const float* prec = (const float*)d_in[8];
    float* out = (float*)d_out;
    const int B = in_sizes[0] / Dd;

    precompute_M_kernel<<<Hh, Hh>>>(W1, W2, W3);
    ode_kernel<<<B, 256>>>(x0, W1, u1, b1, W2, b2, W3, b3, prec, out, B);
}

// round 8
// speedup vs baseline: 1.7223x; 1.1522x over previous
#include <cuda_runtime.h>
#include <cstdint>

// VINeuralODE: B=128, D=32, H=128, 8 Dopri5 steps x 6 field evals.
// dlogpdt = -tr(W3 D2 W2 D1 W1) = -sum_u d1_u (M[u,:]·d2), M precomputed.
// Warp-specialized: warps 0-3 compute h1/h2; warp 4 does W3 quarter + dxdt
// assembly + dopri5 state update; warps 5-7 do W3 quarters + M-row trace dots.
// All dots use packed fma.rn.f32x2 with ld.shared.v2.u64 operands.

#define Dd 32
#define Hh 128
#define NSTEPS 8
#define NST 48

__device__ __align__(16) float d_M[Hh * Hh];

__constant__ float c_C[6]  = {0.0f, 0.2f, 0.3f, 0.8f, 0.88888888888888888f, 1.0f};
__constant__ float c_BW[6] = {35.0f/384.0f, 0.0f, 500.0f/1113.0f, 125.0f/192.0f,
                              -2187.0f/6784.0f, 11.0f/84.0f};

#define BAR_SYNC(id, cnt)   asm volatile("bar.sync %0, %1;"   :: "r"(id), "r"(cnt) : "memory")
#define BAR_ARRIVE(id, cnt) asm volatile("bar.arrive %0, %1;" :: "r"(id), "r"(cnt) : "memory")

__global__ void precompute_M_kernel(const float* __restrict__ W1,
                                    const float* __restrict__ W2,
                                    const float* __restrict__ W3) {
    int jj = blockIdx.x;
    int kk = threadIdx.x;
    float a = 0.f;
#pragma unroll
    for (int i = 0; i < Dd; ++i)
        a += W1[kk * Dd + i] * W3[i * Hh + jj];
    d_M[kk * Hh + jj] = a * W2[jj * Hh + kk];
}

__device__ __forceinline__ float ftanh(float x) {
    float e = __expf(2.0f * x);
    return 1.0f - __fdividef(2.0f, e + 1.0f);
}

__device__ __forceinline__ uint64_t ffma2(uint64_t a, uint64_t b, uint64_t c) {
    uint64_t d;
    asm("fma.rn.f32x2 %0, %1, %2, %3;" : "=l"(d) : "l"(a), "l"(b), "l"(c));
    return d;
}
__device__ __forceinline__ uint64_t pk2(float x, float y) {
    uint64_t r; asm("mov.b64 %0, {%1, %2};" : "=l"(r) : "f"(x), "f"(y)); return r;
}
__device__ __forceinline__ float hsum2(uint64_t v) {
    float a, b; asm("mov.b64 {%0, %1}, %2;" : "=f"(a), "=f"(b) : "l"(v)); return a + b;
}
__device__ __forceinline__ uint32_t sptr(const void* p) {
    return (uint32_t)__cvta_generic_to_shared(p);
}

// 128-length dot: weights packed (64 x u64), activations in shared at saddr.
__device__ __forceinline__ float dot128(const uint64_t* __restrict__ w, uint32_t saddr) {
    uint64_t a0 = 0, a1 = 0, a2 = 0, a3 = 0;
#pragma unroll
    for (int i = 0; i < 32; i += 2) {
        uint64_t p0, p1, p2, p3;
        asm volatile("ld.shared.v2.u64 {%0, %1}, [%2];" : "=l"(p0), "=l"(p1) : "r"(saddr + 16u * i));
        asm volatile("ld.shared.v2.u64 {%0, %1}, [%2];" : "=l"(p2), "=l"(p3) : "r"(saddr + 16u * i + 16u));
        a0 = ffma2(w[2*i],   p0, a0);
        a1 = ffma2(w[2*i+1], p1, a1);
        a2 = ffma2(w[2*i+2], p2, a2);
        a3 = ffma2(w[2*i+3], p3, a3);
    }
    return (hsum2(a0) + hsum2(a1)) + (hsum2(a2) + hsum2(a3));
}

// 32-length dot: weights packed (16 x u64), activations in shared at saddr.
__device__ __forceinline__ float dot32(const uint64_t* __restrict__ w, uint32_t saddr) {
    uint64_t a0 = 0, a1 = 0;
#pragma unroll
    for (int i = 0; i < 8; ++i) {
        uint64_t p0, p1;
        asm volatile("ld.shared.v2.u64 {%0, %1}, [%2];" : "=l"(p0), "=l"(p1) : "r"(saddr + 16u * i));
        a0 = ffma2(w[2*i],   p0, a0);
        a1 = ffma2(w[2*i+1], p1, a1);
    }
    return hsum2(a0) + hsum2(a1);
}

__global__ __launch_bounds__(256, 1)
void ode_kernel(const float* __restrict__ x0,
                const float* __restrict__ W1,
                const float* __restrict__ u1,
                const float* __restrict__ b1,
                const float* __restrict__ W2,
                const float* __restrict__ b2,
                const float* __restrict__ W3,
                const float* __restrict__ b3,
                const float* __restrict__ prec,
                float* __restrict__ out, int B) {
    const int s    = blockIdx.x;
    const int tid  = threadIdx.x;
    const int lane = tid & 31;
    const int warp = tid >> 5;
    const float dt = 1.0f / NSTEPS;
    const float HALF_LOG2PI = 0.9189385332046727f;

    __shared__ __align__(16) float sh_xs[Dd];
    __shared__ __align__(16) float sh_h1[Hh];
    __shared__ __align__(16) float sh_d1[2][Hh];
    __shared__ __align__(16) float sh_h2[Hh];
    __shared__ __align__(16) float sh_d2[Hh];
    __shared__ float sh_dxp[Hh];          // W3 quarter partials (warps 5-7 -> idx 32..127)
    __shared__ float sh_tw[NST][4];       // per-stage trace warp-sums
    __shared__ float sh_xh[NST + 1][Dd];  // x snapshot per stage (written by warp4)
    __shared__ float sh_kd[NST][Dd];      // dxdt per stage
    __shared__ float b1s[Hh], u1s[Hh], b2s[Hh], b3s[Dd], precs[Dd];
    __shared__ float sh_pld[8], sh_pkl[8], sh_lp;

    const uint32_t a_xs = sptr(sh_xs);
    const uint32_t a_h1 = sptr(sh_h1);
    const uint32_t a_h2 = sptr(sh_h2);
    const uint32_t a_d2 = sptr(sh_d2);

    if (tid < Hh) { b1s[tid] = b1[tid]; u1s[tid] = u1[tid]; b2s[tid] = b2[tid]; }
    if (tid < Dd) {
        b3s[tid] = b3[tid]; precs[tid] = prec[tid];
        float xv = x0[s * Dd + tid];
        sh_xs[tid] = xv;
        sh_xh[0][tid] = xv;
    }
    __syncthreads();

    if (warp < 4) {
        // ================= COMPUTE (threads 0-127), H-row j = tid ============
        const int j = tid;
        uint64_t w1p[16];   // W1[j,0:32] packed
        uint64_t w2p[64];   // W2[j,0:128] packed
        {
            const float4* p = (const float4*)(W1 + j * Dd);
#pragma unroll
            for (int i = 0; i < 8; ++i) {
                float4 v = p[i];
                w1p[2*i] = pk2(v.x, v.y); w1p[2*i+1] = pk2(v.z, v.w);
            }
        }
        {
            const float4* p = (const float4*)(W2 + j * Hh);
#pragma unroll
            for (int i = 0; i < 32; ++i) {
                float4 v = p[i];
                w2p[2*i] = pk2(v.x, v.y); w2p[2*i+1] = pk2(v.z, v.w);
            }
        }
        const float b1j = b1s[j], u1j = u1s[j], b2j = b2s[j];

#pragma unroll 1
        for (int gst = 0; gst < NST; ++gst) {
            const int st = gst % 6;
            const int stp = gst / 6;
            float ts = ((float)stp + c_C[st]) * dt;

            BAR_SYNC(5, 160);                         // xs ready (from warp4 / prime)
            // ---- h1 ----
            float a = dot32(w1p, a_xs) + b1j + ts * u1j;
            float h1 = ftanh(a);
            sh_h1[j] = h1;
            sh_d1[gst & 1][j] = 1.f - h1 * h1;
            BAR_SYNC(1, 128);                         // all h1 written
            // ---- h2 ----
            float b = dot128(w2p, a_h1) + b2j;
            float h2 = ftanh(b);
            BAR_SYNC(3, 256);                         // trace consumed old h2/d2
            sh_h2[j] = h2;
            sh_d2[j] = 1.f - h2 * h2;
            BAR_ARRIVE(2, 256);                       // h2/d2 ready
        }
    } else {
        // ================= TRACE (threads 128-255) ===========================
        const int u  = tid - 128;        // 0..127
        const int tw = warp - 4;         // 0..3 (W3 column quarter)
        const int rw = u & 31;           // W3 output row
        uint64_t wmp[64];   // M[u,0:128] packed
        uint64_t w3p[16];   // W3[rw, tw*32 : +32] packed
        {
            const float4* p = (const float4*)(d_M + u * Hh);
#pragma unroll
            for (int i = 0; i < 32; ++i) {
                float4 v = p[i];
                wmp[2*i] = pk2(v.x, v.y); wmp[2*i+1] = pk2(v.z, v.w);
            }
        }
        {
            const float4* p = (const float4*)(W3 + rw * Hh + tw * 32);
#pragma unroll
            for (int i = 0; i < 8; ++i) {
                float4 v = p[i];
                w3p[2*i] = pk2(v.x, v.y); w3p[2*i+1] = pk2(v.z, v.w);
            }
        }
        float yv = 0.f, k0 = 0.f, k1 = 0.f, k2 = 0.f, k3 = 0.f, k4 = 0.f;
        if (tw == 0) yv = x0[s * Dd + lane];

        // prime barriers
        BAR_ARRIVE(3, 256);                           // "d2 consumed"
        if (tw == 0) BAR_ARRIVE(5, 160);              // "xs ready" (init xs = x0)

#pragma unroll 1
        for (int gst = 0; gst < NST; ++gst) {
            const int st = gst % 6;
            BAR_SYNC(2, 256);                         // h2/d2 ready

            // ---- W3 quarter dot: row rw, cols tw*32..+31 ----
            float qd = dot32(w3p, a_h2 + 4u * (tw * 32));

            if (tw == 0) {
                // warp 4: gather partials, dxdt, dopri5 update
                BAR_SYNC(4, 128);                     // warps 5-7 partials ready
                float dxv = qd + ((sh_dxp[32 + lane] + sh_dxp[64 + lane])
                                + sh_dxp[96 + lane]) + b3s[lane];
                sh_kd[gst][lane] = dxv;
                float acc;
                switch (st) {
                    case 0: k0 = dxv; acc = 0.2f * k0; break;
                    case 1: k1 = dxv; acc = (3.f/40.f) * k0 + (9.f/40.f) * k1; break;
                    case 2: k2 = dxv; acc = (44.f/45.f) * k0 + (-56.f/15.f) * k1 + (32.f/9.f) * k2; break;
                    case 3: k3 = dxv; acc = (19372.f/6561.f) * k0 + (-25360.f/2187.f) * k1
                                          + (64448.f/6561.f) * k2 + (-212.f/729.f) * k3; break;
                    case 4: k4 = dxv; acc = (9017.f/3168.f) * k0 + (-355.f/33.f) * k1
                                          + (46732.f/5247.f) * k2 + (49.f/176.f) * k3
                                          + (-5103.f/18656.f) * k4; break;
                    default:
                        yv = yv + dt * ( (35.f/384.f)     * k0
                                       + (500.f/1113.f)   * k2
                                       + (125.f/192.f)    * k3
                                       + (-2187.f/6784.f) * k4
                                       + (11.f/84.f)      * dxv );
                        acc = 0.f; break;
                }
                float xnew = (st < 5) ? (yv + dt * acc) : yv;
                sh_xs[lane] = xnew;
                sh_xh[gst + 1][lane] = xnew;
                BAR_ARRIVE(5, 160);                   // xs ready
            } else {
                sh_dxp[u] = qd;
                BAR_ARRIVE(4, 128);                   // partial ready for warp 4
            }

            // ---- M-row trace dot (off critical path) ----
            float val = sh_d1[gst & 1][u] * dot128(wmp, a_d2);
            BAR_ARRIVE(3, 256);                       // d2 consumed

#pragma unroll
            for (int off = 16; off > 0; off >>= 1)
                val += __shfl_xor_sync(0xffffffffu, val, off);
            if (lane == 0) sh_tw[gst][tw] = val;
        }
        if (tw == 0) out[s * Dd + lane] = yv;         // final z
    }
    __syncthreads();

    // ================= FINAL EPILOGUE: 48 stage reductions over 8 warps ======
    {
        float acc_ld = 0.f, acc_kl = 0.f;
#pragma unroll 1
        for (int i = 0; i < 6; ++i) {
            int g = warp + 8 * i;
            int st = g % 6;
            int stp = g / 6;
            float ts = ((float)stp + c_C[st]) * dt;
            float dlogp = -((sh_tw[g][0] + sh_tw[g][1]) + (sh_tw[g][2] + sh_tw[g][3]));
            float omt = 1.f - ts;
            float cA = -0.5f * omt * omt;
            float cB = -0.5f * omt * (1.f + ts);
            float xv  = sh_xh[g][lane];
            float dxv = sh_kd[g][lane];
            float qv = (cA * (-0.5f * xv * xv - HALF_LOG2PI) + cB * (-precs[lane] * xv)) * dxv;
#pragma unroll
            for (int off = 16; off > 0; off >>= 1)
                qv += __shfl_xor_sync(0xffffffffu, qv, off);
            float bw = c_BW[st];
            acc_ld += bw * dlogp;
            acc_kl += bw * (qv + omt * dlogp);
        }
        if (lane == 0) { sh_pld[warp] = acc_ld; sh_pkl[warp] = acc_kl; }
        if (warp == 1) {
            float xv = x0[s * Dd + lane];
            float lp = -0.5f * xv * xv - HALF_LOG2PI;
#pragma unroll
            for (int off = 16; off > 0; off >>= 1)
                lp += __shfl_xor_sync(0xffffffffu, lp, off);
            if (lane == 0) sh_lp = lp;
        }
    }
    __syncthreads();
    if (tid == 0) {
        float ld = 0.f, kl = 0.f;
#pragma unroll
        for (int w = 0; w < 8; ++w) { ld += sh_pld[w]; kl += sh_pkl[w]; }
        out[B * Dd + s]     = sh_lp + dt * ld;
        out[B * Dd + B + s] = dt * kl;
    }
}

extern "C" void kernel_launch(void* const* d_in, const int* in_sizes, int n_in,
                              void* d_out, int out_size) {
    const float* x0   = (const float*)d_in[0];
    const float* W1   = (const float*)d_in[1];
    const float* u1   = (const float*)d_in[2];
    const float* b1   = (const float*)d_in[3];
    const float* W2   = (const float*)d_in[4];
    const float* b2   = (const float*)d_in[5];
    const float* W3   = (const float*)d_in[6];
    const float* b3   = (const float*)d_in[7];
    const float* prec = (const float*)d_in[8];
    float* out = (float*)d_out;
    const int B = in_sizes[0] / Dd;

    precompute_M_kernel<<<Hh, Hh>>>(W1, W2, W3);
    ode_kernel<<<B, 256>>>(x0, W1, u1, b1, W2, b2, W3, b3, prec, out, B);
}